// round 2
// baseline (speedup 1.0000x reference)
#include <cuda_runtime.h>

#define NMAX 50000
#define EMAX 800000
// D = 128, ED = 64, H = 4, U = 32, HU = 128

// ---- scratch (device globals) ----
__device__ float g_q [NMAX * 128];
__device__ float g_k [NMAX * 128];
__device__ float g_v [NMAX * 128];
__device__ float g_mk[NMAX * 256];   // Mk[n][h*64 + c]
__device__ float g_kb[NMAX * 4];     // kb[n][h]
__device__ int   g_rowptr[NMAX + 1];

// packed f32x2 helpers (sm_103a; ptxas never auto-fuses — PTX only)
__device__ __forceinline__ unsigned long long pack2(float x, float y) {
    unsigned long long r;
    asm("mov.b64 %0, {%1, %2};" : "=l"(r) : "f"(x), "f"(y));
    return r;
}
__device__ __forceinline__ void fma2(unsigned long long& d,
                                     unsigned long long a, unsigned long long b) {
    asm("fma.rn.f32x2 %0, %1, %2, %0;" : "+l"(d) : "l"(a), "l"(b));
}
__device__ __forceinline__ float2 unpack2(unsigned long long p) {
    float2 r;
    asm("mov.b64 {%0, %1}, %2;" : "=f"(r.x), "=f"(r.y) : "l"(p));
    return r;
}

// ============================================================================
// K1: q,k,v = X @ W{q,k,v} + b — [N,128]@[128,128], blockIdx.y selects matrix.
//     BM=128, BN=128, BK=32, 256 threads, 8x8 register tile, f32x2 FMA core.
// ============================================================================
__global__ __launch_bounds__(256) void qkv_gemm_kernel(
    const float* __restrict__ X,
    const float* __restrict__ Wq, const float* __restrict__ bq,
    const float* __restrict__ Wk, const float* __restrict__ bk,
    const float* __restrict__ Wv, const float* __restrict__ bv,
    int N)
{
    __shared__ float As[32][129];   // [k][m], padded
    __shared__ float Bs[32][128];   // [k][n]

    const float* W; const float* bias; float* Out;
    if (blockIdx.y == 0)      { W = Wq; bias = bq; Out = g_q; }
    else if (blockIdx.y == 1) { W = Wk; bias = bk; Out = g_k; }
    else                      { W = Wv; bias = bv; Out = g_v; }

    const int row0 = blockIdx.x * 128;
    const int tid  = threadIdx.x;
    const int tx   = tid & 15;    // m-group
    const int ty   = tid >> 4;    // n-group

    // acc pairs along j: acc2[i][jp] holds (j=2jp, j=2jp+1)
    unsigned long long acc2[8][4];
#pragma unroll
    for (int i = 0; i < 8; i++)
#pragma unroll
        for (int j = 0; j < 4; j++) acc2[i][j] = 0ull;

    for (int kt = 0; kt < 128; kt += 32) {
#pragma unroll
        for (int i = 0; i < 4; i++) {
            int r = (tid >> 3) + i * 32;
            int c = (tid & 7) * 4;
            float4 a = make_float4(0.f, 0.f, 0.f, 0.f);
            if (row0 + r < N)
                a = *(const float4*)(X + (row0 + r) * 128 + kt + c);
            As[c + 0][r] = a.x;
            As[c + 1][r] = a.y;
            As[c + 2][r] = a.z;
            As[c + 3][r] = a.w;
        }
#pragma unroll
        for (int i = 0; i < 4; i++) {
            int kk = (tid >> 5) + i * 8;
            int nn = (tid & 31) * 4;
            *(float4*)&Bs[kk][nn] = *(const float4*)(W + (kt + kk) * 128 + nn);
        }
        __syncthreads();
#pragma unroll
        for (int k = 0; k < 32; k++) {
            unsigned long long a2[8], b2[4];
#pragma unroll
            for (int i = 0; i < 8; i++) {
                float a = As[k][tx * 8 + i];
                a2[i] = pack2(a, a);
            }
            // b pairs: contiguous in Bs, 16B-aligned
            {
                const ulonglong2* p = (const ulonglong2*)&Bs[k][ty * 8];
                ulonglong2 u0 = p[0], u1 = p[1];
                b2[0] = u0.x; b2[1] = u0.y; b2[2] = u1.x; b2[3] = u1.y;
            }
#pragma unroll
            for (int i = 0; i < 8; i++)
#pragma unroll
                for (int jp = 0; jp < 4; jp++)
                    fma2(acc2[i][jp], a2[i], b2[jp]);
        }
        __syncthreads();
    }

#pragma unroll
    for (int i = 0; i < 8; i++) {
        int r = row0 + tx * 8 + i;
        if (r < N) {
            float o[8];
#pragma unroll
            for (int jp = 0; jp < 4; jp++) {
                float2 u = unpack2(acc2[i][jp]);
                o[2 * jp]     = u.x + bias[ty * 8 + 2 * jp];
                o[2 * jp + 1] = u.y + bias[ty * 8 + 2 * jp + 1];
            }
            *(float4*)(Out + r * 128 + ty * 8)     = make_float4(o[0], o[1], o[2], o[3]);
            *(float4*)(Out + r * 128 + ty * 8 + 4) = make_float4(o[4], o[5], o[6], o[7]);
        }
    }
}

// ============================================================================
// K2: Mk[n,h,c] = sum_u We[c, h*32+u] * k[n,h,u];  kb[n,h] = sum_u be[hu]*k[n,h,u]
//     We row held in registers per thread; ks read via LDS broadcast; f32x2.
// ============================================================================
__global__ __launch_bounds__(256) void mk_kernel(
    const float* __restrict__ We, const float* __restrict__ be, int N)
{
    __shared__ float sWe[64 * 128];
    __shared__ float ks[16][128];

    const int tid = threadIdx.x;
    const int n0  = blockIdx.x * 16;
    const int h   = tid >> 6, c = tid & 63;

    for (int i = tid; i < 64 * 128 / 4; i += 256)
        ((float4*)sWe)[i] = ((const float4*)We)[i];
    for (int i = tid; i < 16 * 128 / 4; i += 256) {
        int nl  = i >> 5;
        int off = (i & 31) * 4;
        float4 val = make_float4(0.f, 0.f, 0.f, 0.f);
        if (n0 + nl < N) val = *(const float4*)(g_k + (n0 + nl) * 128 + off);
        *(float4*)&ks[nl][off] = val;
    }
    __syncthreads();

    // per-thread We row: 32 floats = 16 packed pairs
    unsigned long long w2[16];
#pragma unroll
    for (int u2 = 0; u2 < 16; u2++)
        w2[u2] = *(const unsigned long long*)&sWe[c * 128 + h * 32 + 2 * u2];

#pragma unroll 1
    for (int nl = 0; nl < 16; nl++) {
        if (n0 + nl >= N) break;
        unsigned long long s2 = 0ull;
#pragma unroll
        for (int u2 = 0; u2 < 16; u2++) {
            unsigned long long kp = *(const unsigned long long*)&ks[nl][h * 32 + 2 * u2];
            fma2(s2, kp, w2[u2]);
        }
        float2 u = unpack2(s2);
        g_mk[(n0 + nl) * 256 + h * 64 + c] = u.x + u.y;
    }
    if (tid < 64) {
        int nl = tid >> 2, h2 = tid & 3;
        if (n0 + nl < N) {
            float s = 0.f;
#pragma unroll
            for (int u = 0; u < 32; u++)
                s = fmaf(be[h2 * 32 + u], ks[nl][h2 * 32 + u], s);
            g_kb[(n0 + nl) * 4 + h2] = s;
        }
    }
}

// ============================================================================
// K3: rowptr[n] = lower_bound(src, n)  (src sorted)
// ============================================================================
__global__ void rowptr_kernel(const int* __restrict__ src, int E, int N)
{
    int n = blockIdx.x * blockDim.x + threadIdx.x;
    if (n > N) return;
    int lo = 0, hi = E;
    while (lo < hi) {
        int mid = (lo + hi) >> 1;
        if (src[mid] < n) lo = mid + 1; else hi = mid;
    }
    g_rowptr[n] = lo;
}

// ============================================================================
// K4: fused per-node edge pass — one warp per source node.
//     Head-group-local reductions: lane l = (hl = l>>3, sl = l&7)
//       * owns hu = 4l..4l+3 for q·k and v
//       * owns c  = 8sl..8sl+7 of head hl for the edge-feature term
//     → both partials reduce with the SAME 3 xor-shuffles (was 23 SHFL/edge).
//     EF & q streamed with __ldcs so gather tables stay L2-resident.
// ============================================================================
__global__ __launch_bounds__(256) void edge_attn_kernel(
    const float* __restrict__ EF, const int* __restrict__ dst,
    const float* __restrict__ Wo, const float* __restrict__ bo,
    float* __restrict__ out, int N)
{
    __shared__ float sWo[128 * 32];
    __shared__ float sbo[32];
    const int tid = threadIdx.x;
    for (int i = tid; i < 1024; i += 256)
        ((float4*)sWo)[i] = ((const float4*)Wo)[i];
    if (tid < 32) sbo[tid] = bo[tid];
    __syncthreads();

    const int lane = tid & 31, warp = tid >> 5;
    const int n = blockIdx.x * 8 + warp;
    if (n >= N) return;

    const int hl = lane >> 3;
    const int sl = lane & 7;
    const float4 q4 = __ldcs((const float4*)(g_q + n * 128 + lane * 4));
    const int e0 = g_rowptr[n], e1 = g_rowptr[n + 1];

    float  m    = -1e30f;
    float  sexp = 0.f;
    float4 acc  = make_float4(0.f, 0.f, 0.f, 0.f);

    int d = (e0 < e1) ? dst[e0] : 0;
    for (int e = e0; e < e1; e++) {
        const int d_next = (e + 1 < e1) ? dst[e + 1] : 0;

        const float4 k4  = *(const float4*)(g_k + d * 128 + lane * 4);
        const float4 mkA = *(const float4*)(g_mk + d * 256 + hl * 64 + sl * 8);
        const float4 mkB = *(const float4*)(g_mk + d * 256 + hl * 64 + sl * 8 + 4);
        const float4 efA = __ldcs((const float4*)(EF + e * 64 + sl * 8));
        const float4 efB = __ldcs((const float4*)(EF + e * 64 + sl * 8 + 4));
        const float  kbv = g_kb[d * 4 + hl];
        const float4 v4  = *(const float4*)(g_v + d * 128 + lane * 4);

        // q·k partial (lane's 4 hu) + edge partial (lane's 8 c of head hl)
        float t = q4.x * k4.x + q4.y * k4.y + q4.z * k4.z + q4.w * k4.w;
        t = fmaf(efA.x, mkA.x, t); t = fmaf(efA.y, mkA.y, t);
        t = fmaf(efA.z, mkA.z, t); t = fmaf(efA.w, mkA.w, t);
        t = fmaf(efB.x, mkB.x, t); t = fmaf(efB.y, mkB.y, t);
        t = fmaf(efB.z, mkB.z, t); t = fmaf(efB.w, mkB.w, t);
        // reduce within the 8-lane head group
        t += __shfl_xor_sync(0xffffffffu, t, 1);
        t += __shfl_xor_sync(0xffffffffu, t, 2);
        t += __shfl_xor_sync(0xffffffffu, t, 4);
        const float s = t + kbv;

        // online softmax update
        const float mnew  = fmaxf(m, s);
        const float scale = __expf(m - mnew);
        const float w     = __expf(s - mnew);
        sexp  = fmaf(sexp,  scale, w);
        acc.x = fmaf(acc.x, scale, w * v4.x);
        acc.y = fmaf(acc.y, scale, w * v4.y);
        acc.z = fmaf(acc.z, scale, w * v4.z);
        acc.w = fmaf(acc.w, scale, w * v4.w);
        m = mnew;
        d = d_next;
    }

    const float inv = (sexp > 0.f) ? (1.0f / sexp) : 0.f;
    acc.x *= inv; acc.y *= inv; acc.z *= inv; acc.w *= inv;

    // output epilogue: out[n, j=lane] = relu(sum_hu attended[hu]*Wo[hu,j] + bo[j])
    float o = sbo[lane];
#pragma unroll
    for (int p = 0; p < 32; p++) {
        const float ax = __shfl_sync(0xffffffffu, acc.x, p);
        const float ay = __shfl_sync(0xffffffffu, acc.y, p);
        const float az = __shfl_sync(0xffffffffu, acc.z, p);
        const float aw = __shfl_sync(0xffffffffu, acc.w, p);
        o = fmaf(ax, sWo[(4 * p + 0) * 32 + lane], o);
        o = fmaf(ay, sWo[(4 * p + 1) * 32 + lane], o);
        o = fmaf(az, sWo[(4 * p + 2) * 32 + lane], o);
        o = fmaf(aw, sWo[(4 * p + 3) * 32 + lane], o);
    }
    out[n * 32 + lane] = fmaxf(o, 0.f);
}

// ============================================================================
// launch
// ============================================================================
extern "C" void kernel_launch(void* const* d_in, const int* in_sizes, int n_in,
                              void* d_out, int out_size)
{
    const float* X  = (const float*)d_in[0];
    const int*   EI = (const int*)  d_in[1];   // [2,E]: src then dst
    const float* EF = (const float*)d_in[2];
    const float* Wq = (const float*)d_in[3];
    const float* bq = (const float*)d_in[4];
    const float* Wk = (const float*)d_in[5];
    const float* bk = (const float*)d_in[6];
    const float* Wv = (const float*)d_in[7];
    const float* bv = (const float*)d_in[8];
    const float* We = (const float*)d_in[9];
    const float* be = (const float*)d_in[10];
    const float* Wo = (const float*)d_in[11];
    const float* bo = (const float*)d_in[12];

    const int N = in_sizes[0] / 128;
    const int E = in_sizes[1] / 2;

    dim3 g1((N + 127) / 128, 3);
    qkv_gemm_kernel<<<g1, 256>>>(X, Wq, bq, Wk, bk, Wv, bv, N);
    mk_kernel<<<(N + 15) / 16, 256>>>(We, be, N);
    rowptr_kernel<<<(N + 1 + 255) / 256, 256>>>(EI, E, N);
    edge_attn_kernel<<<(N + 7) / 8, 256>>>(EF, EI + E, Wo, bo, (float*)d_out, N);
}

// round 3
// speedup vs baseline: 1.2669x; 1.2669x over previous
#include <cuda_runtime.h>
#include <cuda_fp16.h>

#define NMAX 50000
#define EMAX 800000
// D = 128, ED = 64, H = 4, U = 32, HU = 128

// ---- scratch (device globals) ----
__device__ float  g_q  [NMAX * 128];
__device__ __half g_kh [NMAX * 128];
__device__ __half g_vh [NMAX * 128];
__device__ __half g_mkh[NMAX * 256];   // Mk[n][h*64 + c], fp16
__device__ float  g_kb [NMAX * 4];     // kb[n][h]
__device__ int    g_rowptr[NMAX + 1];

// ============================================================================
// K1: q,k,v = X @ W{q,k,v} + b — [N,128]@[128,128], blockIdx.y selects matrix.
//     Scalar fp32 FFMA register tile (round-1 form). q written fp32; k,v fp16.
// ============================================================================
__global__ __launch_bounds__(256) void qkv_gemm_kernel(
    const float* __restrict__ X,
    const float* __restrict__ Wq, const float* __restrict__ bq,
    const float* __restrict__ Wk, const float* __restrict__ bk,
    const float* __restrict__ Wv, const float* __restrict__ bv,
    int N)
{
    __shared__ float As[32][129];   // [k][m], padded
    __shared__ float Bs[32][128];   // [k][n]

    const float* W; const float* bias;
    if (blockIdx.y == 0)      { W = Wq; bias = bq; }
    else if (blockIdx.y == 1) { W = Wk; bias = bk; }
    else                      { W = Wv; bias = bv; }
    const bool isQ = (blockIdx.y == 0);
    __half* OutH = (blockIdx.y == 1) ? g_kh : g_vh;

    const int row0 = blockIdx.x * 128;
    const int tid  = threadIdx.x;
    const int tx   = tid & 15;    // m-group
    const int ty   = tid >> 4;    // n-group

    float acc[8][8];
#pragma unroll
    for (int i = 0; i < 8; i++)
#pragma unroll
        for (int j = 0; j < 8; j++) acc[i][j] = 0.f;

    for (int kt = 0; kt < 128; kt += 32) {
#pragma unroll
        for (int i = 0; i < 4; i++) {
            int r = (tid >> 3) + i * 32;
            int c = (tid & 7) * 4;
            float4 a = make_float4(0.f, 0.f, 0.f, 0.f);
            if (row0 + r < N)
                a = *(const float4*)(X + (row0 + r) * 128 + kt + c);
            As[c + 0][r] = a.x;
            As[c + 1][r] = a.y;
            As[c + 2][r] = a.z;
            As[c + 3][r] = a.w;
        }
#pragma unroll
        for (int i = 0; i < 4; i++) {
            int kk = (tid >> 5) + i * 8;
            int nn = (tid & 31) * 4;
            *(float4*)&Bs[kk][nn] = *(const float4*)(W + (kt + kk) * 128 + nn);
        }
        __syncthreads();
#pragma unroll
        for (int k = 0; k < 32; k++) {
            float a[8], b[8];
#pragma unroll
            for (int i = 0; i < 8; i++) a[i] = As[k][tx * 8 + i];
            *(float4*)&b[0] = *(float4*)&Bs[k][ty * 8];
            *(float4*)&b[4] = *(float4*)&Bs[k][ty * 8 + 4];
#pragma unroll
            for (int i = 0; i < 8; i++)
#pragma unroll
                for (int j = 0; j < 8; j++)
                    acc[i][j] = fmaf(a[i], b[j], acc[i][j]);
        }
        __syncthreads();
    }

#pragma unroll
    for (int i = 0; i < 8; i++) {
        int r = row0 + tx * 8 + i;
        if (r < N) {
            float o[8];
#pragma unroll
            for (int j = 0; j < 8; j++) o[j] = acc[i][j] + bias[ty * 8 + j];
            if (isQ) {
                *(float4*)(g_q + r * 128 + ty * 8)     = make_float4(o[0], o[1], o[2], o[3]);
                *(float4*)(g_q + r * 128 + ty * 8 + 4) = make_float4(o[4], o[5], o[6], o[7]);
            } else {
                __half2 h[4];
                h[0] = __float22half2_rn(make_float2(o[0], o[1]));
                h[1] = __float22half2_rn(make_float2(o[2], o[3]));
                h[2] = __float22half2_rn(make_float2(o[4], o[5]));
                h[3] = __float22half2_rn(make_float2(o[6], o[7]));
                *(uint4*)(OutH + r * 128 + ty * 8) = *(uint4*)h;
            }
        }
    }
}

// ============================================================================
// K2: Mk[n,h,c] = sum_u We[c, h*32+u] * k[n,h,u] (fp16 out);
//     kb[n,h] = sum_u be[hu]*k[n,h,u]
// ============================================================================
__global__ __launch_bounds__(256) void mk_kernel(
    const float* __restrict__ We, const float* __restrict__ be, int N)
{
    __shared__ float WeT[128][65];   // [hu][c], padded
    __shared__ float ks[16][128];

    const int tid = threadIdx.x;
    const int n0  = blockIdx.x * 16;

    for (int i = tid; i < 64 * 128; i += 256) {
        int c  = i >> 7;
        int hu = i & 127;
        WeT[hu][c] = We[i];
    }
    for (int i = tid; i < 16 * 64; i += 256) {   // half2 granules
        int nl  = i >> 6;
        int off = (i & 63) * 2;
        __half2 hv = __half2half2(__float2half(0.f));
        if (n0 + nl < N) hv = *(const __half2*)(g_kh + (n0 + nl) * 128 + off);
        float2 f = __half22float2(hv);
        ks[nl][off]     = f.x;
        ks[nl][off + 1] = f.y;
    }
    __syncthreads();

    const int h = tid >> 6, c = tid & 63;
#pragma unroll 1
    for (int nl = 0; nl < 16; nl++) {
        if (n0 + nl >= N) break;
        float s = 0.f;
#pragma unroll
        for (int u = 0; u < 32; u++)
            s = fmaf(ks[nl][h * 32 + u], WeT[h * 32 + u][c], s);
        g_mkh[(n0 + nl) * 256 + h * 64 + c] = __float2half_rn(s);
    }
    if (tid < 64) {
        int nl = tid >> 2, h2 = tid & 3;
        if (n0 + nl < N) {
            float s = 0.f;
#pragma unroll
            for (int u = 0; u < 32; u++)
                s = fmaf(be[h2 * 32 + u], ks[nl][h2 * 32 + u], s);
            g_kb[(n0 + nl) * 4 + h2] = s;
        }
    }
}

// ============================================================================
// K3: rowptr[n] = lower_bound(src, n)  (src sorted)
// ============================================================================
__global__ void rowptr_kernel(const int* __restrict__ src, int E, int N)
{
    int n = blockIdx.x * blockDim.x + threadIdx.x;
    if (n > N) return;
    int lo = 0, hi = E;
    while (lo < hi) {
        int mid = (lo + hi) >> 1;
        if (src[mid] < n) lo = mid + 1; else hi = mid;
    }
    g_rowptr[n] = lo;
}

// ============================================================================
// K4: fused per-node edge pass — one warp per source node, unroll-2.
//     fp16 gather tables (k, v, Mk), fp32 accumulation, online softmax.
// ============================================================================

// score + v gather for one edge (hl/sl/q4 from enclosing scope)
#define EDGE_SCORE(eI, dI, sOut, vOut) do {                                      \
    uint2 kr = *(const uint2*)(g_kh + (size_t)(dI) * 128 + lane * 4);            \
    float2 k01 = __half22float2(*(__half2*)&kr.x);                               \
    float2 k23 = __half22float2(*(__half2*)&kr.y);                               \
    uint4 mkr = *(const uint4*)(g_mkh + (size_t)(dI) * 256 + hl * 64 + sl * 8);  \
    float2 m01 = __half22float2(*(__half2*)&mkr.x);                              \
    float2 m23 = __half22float2(*(__half2*)&mkr.y);                              \
    float2 m45 = __half22float2(*(__half2*)&mkr.z);                              \
    float2 m67 = __half22float2(*(__half2*)&mkr.w);                              \
    float4 efA = __ldcs((const float4*)(EF + (size_t)(eI) * 64 + sl * 8));       \
    float4 efB = __ldcs((const float4*)(EF + (size_t)(eI) * 64 + sl * 8 + 4));   \
    uint2 vr = *(const uint2*)(g_vh + (size_t)(dI) * 128 + lane * 4);            \
    float2 v01 = __half22float2(*(__half2*)&vr.x);                               \
    float2 v23 = __half22float2(*(__half2*)&vr.y);                               \
    float t = q4.x * k01.x + q4.y * k01.y + q4.z * k23.x + q4.w * k23.y;         \
    t = fmaf(efA.x, m01.x, t); t = fmaf(efA.y, m01.y, t);                        \
    t = fmaf(efA.z, m23.x, t); t = fmaf(efA.w, m23.y, t);                        \
    t = fmaf(efB.x, m45.x, t); t = fmaf(efB.y, m45.y, t);                        \
    t = fmaf(efB.z, m67.x, t); t = fmaf(efB.w, m67.y, t);                        \
    t += __shfl_xor_sync(0xffffffffu, t, 1);                                     \
    t += __shfl_xor_sync(0xffffffffu, t, 2);                                     \
    t += __shfl_xor_sync(0xffffffffu, t, 4);                                     \
    sOut = t + g_kb[(size_t)(dI) * 4 + hl];                                      \
    vOut = make_float4(v01.x, v01.y, v23.x, v23.y);                              \
} while (0)

__global__ __launch_bounds__(256) void edge_attn_kernel(
    const float* __restrict__ EF, const int* __restrict__ dst,
    const float* __restrict__ Wo, const float* __restrict__ bo,
    float* __restrict__ out, int N)
{
    __shared__ float sWo[128 * 32];
    __shared__ float sbo[32];
    const int tid = threadIdx.x;
    for (int i = tid; i < 1024; i += 256)
        ((float4*)sWo)[i] = ((const float4*)Wo)[i];
    if (tid < 32) sbo[tid] = bo[tid];
    __syncthreads();

    const int lane = tid & 31, warp = tid >> 5;
    const int n = blockIdx.x * 8 + warp;
    if (n >= N) return;

    const int hl = lane >> 3;
    const int sl = lane & 7;
    const float4 q4 = *(const float4*)(g_q + n * 128 + lane * 4);
    const int e0 = g_rowptr[n], e1 = g_rowptr[n + 1];

    float  m    = -1e30f;
    float  sexp = 0.f;
    float4 acc  = make_float4(0.f, 0.f, 0.f, 0.f);

    int e = e0;
#pragma unroll 1
    for (; e + 2 <= e1; e += 2) {
        const int d0 = dst[e], d1 = dst[e + 1];
        float s0, s1; float4 v0, v1;
        EDGE_SCORE(e,     d0, s0, v0);
        EDGE_SCORE(e + 1, d1, s1, v1);

        const float mnew  = fmaxf(m, fmaxf(s0, s1));
        const float scale = __expf(m - mnew);
        const float w0    = __expf(s0 - mnew);
        const float w1    = __expf(s1 - mnew);
        sexp  = fmaf(sexp,  scale, w0 + w1);
        acc.x = fmaf(acc.x, scale, fmaf(w0, v0.x, w1 * v1.x));
        acc.y = fmaf(acc.y, scale, fmaf(w0, v0.y, w1 * v1.y));
        acc.z = fmaf(acc.z, scale, fmaf(w0, v0.z, w1 * v1.z));
        acc.w = fmaf(acc.w, scale, fmaf(w0, v0.w, w1 * v1.w));
        m = mnew;
    }
    if (e < e1) {
        const int d0 = dst[e];
        float s0; float4 v0;
        EDGE_SCORE(e, d0, s0, v0);
        const float mnew  = fmaxf(m, s0);
        const float scale = __expf(m - mnew);
        const float w0    = __expf(s0 - mnew);
        sexp  = fmaf(sexp,  scale, w0);
        acc.x = fmaf(acc.x, scale, w0 * v0.x);
        acc.y = fmaf(acc.y, scale, w0 * v0.y);
        acc.z = fmaf(acc.z, scale, w0 * v0.z);
        acc.w = fmaf(acc.w, scale, w0 * v0.w);
        m = mnew;
    }

    const float inv = (sexp > 0.f) ? (1.0f / sexp) : 0.f;
    acc.x *= inv; acc.y *= inv; acc.z *= inv; acc.w *= inv;

    // output epilogue: out[n, j=lane] = relu(sum_hu attended[hu]*Wo[hu,j] + bo[j])
    float o = sbo[lane];
#pragma unroll
    for (int p = 0; p < 32; p++) {
        const float ax = __shfl_sync(0xffffffffu, acc.x, p);
        const float ay = __shfl_sync(0xffffffffu, acc.y, p);
        const float az = __shfl_sync(0xffffffffu, acc.z, p);
        const float aw = __shfl_sync(0xffffffffu, acc.w, p);
        o = fmaf(ax, sWo[(4 * p + 0) * 32 + lane], o);
        o = fmaf(ay, sWo[(4 * p + 1) * 32 + lane], o);
        o = fmaf(az, sWo[(4 * p + 2) * 32 + lane], o);
        o = fmaf(aw, sWo[(4 * p + 3) * 32 + lane], o);
    }
    out[n * 32 + lane] = fmaxf(o, 0.f);
}

// ============================================================================
// launch
// ============================================================================
extern "C" void kernel_launch(void* const* d_in, const int* in_sizes, int n_in,
                              void* d_out, int out_size)
{
    const float* X  = (const float*)d_in[0];
    const int*   EI = (const int*)  d_in[1];   // [2,E]: src then dst
    const float* EF = (const float*)d_in[2];
    const float* Wq = (const float*)d_in[3];
    const float* bq = (const float*)d_in[4];
    const float* Wk = (const float*)d_in[5];
    const float* bk = (const float*)d_in[6];
    const float* Wv = (const float*)d_in[7];
    const float* bv = (const float*)d_in[8];
    const float* We = (const float*)d_in[9];
    const float* be = (const float*)d_in[10];
    const float* Wo = (const float*)d_in[11];
    const float* bo = (const float*)d_in[12];

    const int N = in_sizes[0] / 128;
    const int E = in_sizes[1] / 2;

    dim3 g1((N + 127) / 128, 3);
    qkv_gemm_kernel<<<g1, 256>>>(X, Wq, bq, Wk, bk, Wv, bv, N);
    mk_kernel<<<(N + 15) / 16, 256>>>(We, be, N);
    rowptr_kernel<<<(N + 1 + 255) / 256, 256>>>(EI, E, N);
    edge_attn_kernel<<<(N + 7) / 8, 256>>>(EF, EI + E, Wo, bo, (float*)d_out, N);
}